// round 5
// baseline (speedup 1.0000x reference)
#include <cuda_runtime.h>
#include <math.h>
#include <stdint.h>

// Shapes: B=4, T=8, RES=32, C=128 -> L=8192, M=32768 rows
// branch0: Hsp=32, Wsp=4 ; branch1: Hsp=4, Wsp=32 ; win=512, nh=4, hd=16

#define M_TOK 32768

typedef unsigned long long u64;

__device__ __forceinline__ u64 ffma2(u64 a, u64 b, u64 c) {
    u64 d;
    asm("fma.rn.f32x2 %0, %1, %2, %3;" : "=l"(d) : "l"(a), "l"(b), "l"(c));
    return d;
}
__device__ __forceinline__ u64 mul2(u64 a, u64 b) {
    u64 d;
    asm("mul.rn.f32x2 %0, %1, %2;" : "=l"(d) : "l"(a), "l"(b));
    return d;
}
__device__ __forceinline__ float2 u2f(u64 a) {
    float2 f;
    asm("mov.b64 {%0, %1}, %2;" : "=f"(f.x), "=f"(f.y) : "l"(a));
    return f;
}
__device__ __forceinline__ u64 f2u(float x, float y) {
    u64 d;
    asm("mov.b64 %0, {%1, %2};" : "=l"(d) : "f"(x), "f"(y));
    return d;
}

// Scratch (static device arrays; no runtime allocation)
__device__ float g_norm[M_TOK * 128];
__device__ float g_qkv [M_TOK * 384];
__device__ float g_att [M_TOK * 128];
__device__ float g_hid [M_TOK * 512];

// ---------------------------------------------------------------------------
// LayerNorm: one warp per 128-channel row
// ---------------------------------------------------------------------------
__global__ void __launch_bounds__(256) ln_kernel(
    const float* __restrict__ x, const float* __restrict__ w,
    const float* __restrict__ b, float* __restrict__ out)
{
    int lane = threadIdx.x & 31;
    int row  = blockIdx.x * 8 + (threadIdx.x >> 5);
    const float4 v = *(const float4*)(x + (size_t)row * 128 + lane * 4);
    float s = v.x + v.y + v.z + v.w;
    #pragma unroll
    for (int o = 16; o; o >>= 1) s += __shfl_xor_sync(0xffffffffu, s, o);
    float mu = s * (1.0f / 128.0f);
    float dx = v.x - mu, dy = v.y - mu, dz = v.z - mu, dw = v.w - mu;
    float sq = dx * dx + dy * dy + dz * dz + dw * dw;
    #pragma unroll
    for (int o = 16; o; o >>= 1) sq += __shfl_xor_sync(0xffffffffu, sq, o);
    float r = rsqrtf(sq * (1.0f / 128.0f) + 1e-5f);
    float4 wv = *(const float4*)(w + lane * 4);
    float4 bv = *(const float4*)(b + lane * 4);
    float4 o4;
    o4.x = dx * r * wv.x + bv.x;
    o4.y = dy * r * wv.y + bv.y;
    o4.z = dz * r * wv.z + bv.z;
    o4.w = dw * r * wv.w + bv.w;
    *(float4*)(out + (size_t)row * 128 + lane * 4) = o4;
}

// ---------------------------------------------------------------------------
// GEMM: out[M,N] = A[M,K] @ W[N,K]^T (+bias)(+gelu)(+res)
// 128x64 tile, 256 threads, 8x4 per thread via FFMA2 (pairs along M),
// BK=16, register-prefetch double buffering.
// A in smem transposed sA[k][m] (pad 132); B in smem pre-duplicated float2.
// ---------------------------------------------------------------------------
template <bool GELU>
__global__ void __launch_bounds__(256) gemm_kernel(
    const float* __restrict__ A, const float* __restrict__ W,
    const float* __restrict__ bias, const float* __restrict__ res,
    float* __restrict__ out, int N, int K)
{
    __shared__ float  sA[16][132];
    __shared__ float2 sB[16][66];

    const int tid = threadIdx.x;
    const int m0 = blockIdx.y << 7, n0 = blockIdx.x << 6;
    const int tx = tid & 15, ty = tid >> 4;

    // global-load mapping
    const int am0 = tid >> 2,           akc0 = (tid & 3) << 2;
    const int am1 = (tid + 256) >> 2,   akc1 = (tid & 3) << 2;
    const int bn  = tid >> 2,           bkc  = (tid & 3) << 2;

    const float* Ap0 = A + (size_t)(m0 + am0) * K + akc0;
    const float* Ap1 = A + (size_t)(m0 + am1) * K + akc1;
    const float* Wp  = W + (size_t)(n0 + bn)  * K + bkc;

    u64 acc[4][4];
    #pragma unroll
    for (int i = 0; i < 4; i++)
        #pragma unroll
        for (int j = 0; j < 4; j++) acc[i][j] = 0ull;

    float4 ra0 = *(const float4*)(Ap0);
    float4 ra1 = *(const float4*)(Ap1);
    float4 rb  = *(const float4*)(Wp);

    for (int k0 = 0; k0 < K; k0 += 16) {
        // stage current regs into smem
        sA[akc0 + 0][am0] = ra0.x; sA[akc0 + 1][am0] = ra0.y;
        sA[akc0 + 2][am0] = ra0.z; sA[akc0 + 3][am0] = ra0.w;
        sA[akc1 + 0][am1] = ra1.x; sA[akc1 + 1][am1] = ra1.y;
        sA[akc1 + 2][am1] = ra1.z; sA[akc1 + 3][am1] = ra1.w;
        sB[bkc + 0][bn] = make_float2(rb.x, rb.x);
        sB[bkc + 1][bn] = make_float2(rb.y, rb.y);
        sB[bkc + 2][bn] = make_float2(rb.z, rb.z);
        sB[bkc + 3][bn] = make_float2(rb.w, rb.w);
        __syncthreads();

        // prefetch next k-tile (overlaps with compute)
        if (k0 + 16 < K) {
            ra0 = *(const float4*)(Ap0 + k0 + 16);
            ra1 = *(const float4*)(Ap1 + k0 + 16);
            rb  = *(const float4*)(Wp  + k0 + 16);
        }

        #pragma unroll
        for (int kk = 0; kk < 16; kk++) {
            const ulonglong2* ap = (const ulonglong2*)&sA[kk][ty << 3];
            ulonglong2 aA = ap[0], aB = ap[1];          // 8 M values = 4 pairs
            const ulonglong2* bp = (const ulonglong2*)&sB[kk][tx << 2];
            ulonglong2 bA = bp[0], bB = bp[1];          // 4 duplicated N values
            u64 av[4] = {aA.x, aA.y, aB.x, aB.y};
            u64 bv[4] = {bA.x, bA.y, bB.x, bB.y};
            #pragma unroll
            for (int mp = 0; mp < 4; mp++)
                #pragma unroll
                for (int j = 0; j < 4; j++)
                    acc[mp][j] = ffma2(av[mp], bv[j], acc[mp][j]);
        }
        __syncthreads();
    }

    // epilogue
    float bz[4] = {0.f, 0.f, 0.f, 0.f};
    if (bias) {
        float4 b4 = *(const float4*)(bias + n0 + (tx << 2));
        bz[0] = b4.x; bz[1] = b4.y; bz[2] = b4.z; bz[3] = b4.w;
    }
    #pragma unroll
    for (int mp = 0; mp < 4; mp++) {
        float vlo[4], vhi[4];
        #pragma unroll
        for (int j = 0; j < 4; j++) {
            float2 c = u2f(acc[mp][j]);
            float tl = c.x + bz[j];
            float th = c.y + bz[j];
            if (GELU) {
                tl = 0.5f * tl * (1.0f + erff(tl * 0.70710678118654752f));
                th = 0.5f * th * (1.0f + erff(th * 0.70710678118654752f));
            }
            vlo[j] = tl; vhi[j] = th;
        }
        int rlo = m0 + (ty << 3) + (mp << 1);
        size_t offlo = (size_t)rlo * N + n0 + (tx << 2);
        size_t offhi = offlo + N;
        if (res) {
            float4 r4 = *(const float4*)(res + offlo);
            vlo[0] += r4.x; vlo[1] += r4.y; vlo[2] += r4.z; vlo[3] += r4.w;
            float4 r5 = *(const float4*)(res + offhi);
            vhi[0] += r5.x; vhi[1] += r5.y; vhi[2] += r5.z; vhi[3] += r5.w;
        }
        float4 o4 = {vlo[0], vlo[1], vlo[2], vlo[3]};
        float4 o5 = {vhi[0], vhi[1], vhi[2], vhi[3]};
        *(float4*)(out + offlo) = o4;
        *(float4*)(out + offhi) = o5;
    }
}

// ---------------------------------------------------------------------------
// Attention + fused LePE. One CTA per (branch, window, head).
// Single-pass softmax (no max-subtraction: |score| <= ~2, exp is safe) with
// FFMA2 packed math in both QK^T and AV loops.
// ---------------------------------------------------------------------------
__global__ void __launch_bounds__(256, 2) attn_kernel(
    const float* __restrict__ qkv,
    const float* __restrict__ cw0, const float* __restrict__ cb0,
    const float* __restrict__ cw1, const float* __restrict__ cb1,
    float* __restrict__ att)
{
    extern __shared__ float dsm[];
    float* sK = dsm;            // 512*16
    float* sV = dsm + 8192;     // 512*16
    __shared__ float sCW[27 * 16];
    __shared__ float sCB[16];

    int bid = blockIdx.x;
    int br  = bid >> 8;
    int rem = bid & 255;
    int w   = rem >> 2;
    int n   = rem & 3;
    int b   = w >> 4;
    int tb  = (w >> 3) & 1;
    int hw  = w & 7;
    int tid = threadIdx.x;

    auto tok = [&](int p) -> int {
        int ts = p >> 7, r2 = p & 127;
        if (br == 0) {
            int hs = r2 >> 2, ws = r2 & 3;
            return ((tb * 4 + ts) << 10) + (hs << 5) + (hw << 2) + ws;
        } else {
            int hs = r2 >> 5, ws = r2 & 31;
            return ((tb * 4 + ts) << 10) + (((hw << 2) + hs) << 5) + ws;
        }
    };

    int cq = br * 64 + n * 16;
    int rowbase = b * 8192;

    for (int idx = tid; idx < 2048; idx += 256) {
        int p = idx >> 2, c4 = (idx & 3) << 2;
        const float* base = qkv + (size_t)(rowbase + tok(p)) * 384;
        *(float4*)&sK[p * 16 + c4] = *(const float4*)(base + 128 + cq + c4);
        *(float4*)&sV[p * 16 + c4] = *(const float4*)(base + 256 + cq + c4);
    }
    {
        const float* cw = br ? cw1 : cw0;
        for (int idx = tid; idx < 432; idx += 256) {
            int d = idx / 27, k = idx - d * 27;
            sCW[k * 16 + d] = cw[(n * 16 + d) * 27 + k];
        }
        if (tid < 16) sCB[tid] = (br ? cb1 : cb0)[n * 16 + tid];
    }
    __syncthreads();

    int p0 = tid, p1 = tid + 256;
    int l0t = tok(p0), l1t = tok(p1);

    u64 q0p[8], q1p[8];
    {
        const u64 scale2 = f2u(0.25f, 0.25f);
        const ulonglong2* qv0 =
            (const ulonglong2*)(qkv + (size_t)(rowbase + l0t) * 384 + cq);
        const ulonglong2* qv1 =
            (const ulonglong2*)(qkv + (size_t)(rowbase + l1t) * 384 + cq);
        #pragma unroll
        for (int i = 0; i < 4; i++) {
            ulonglong2 t0 = qv0[i];
            q0p[2 * i]     = mul2(t0.x, scale2);
            q0p[2 * i + 1] = mul2(t0.y, scale2);
            ulonglong2 t1 = qv1[i];
            q1p[2 * i]     = mul2(t1.x, scale2);
            q1p[2 * i + 1] = mul2(t1.y, scale2);
        }
    }

    u64 acc0[8], acc1[8];
    #pragma unroll
    for (int i = 0; i < 8; i++) { acc0[i] = 0ull; acc1[i] = 0ull; }
    float sum0 = 0.f, sum1 = 0.f;

    #pragma unroll 2
    for (int j = 0; j < 512; j++) {
        const ulonglong2* kr = (const ulonglong2*)(sK + (j << 4));
        ulonglong2 kA = kr[0], kB = kr[1], kC = kr[2], kD = kr[3];
        u64 s0 = 0ull, s1 = 0ull;
        s0 = ffma2(q0p[0], kA.x, s0); s0 = ffma2(q0p[1], kA.y, s0);
        s0 = ffma2(q0p[2], kB.x, s0); s0 = ffma2(q0p[3], kB.y, s0);
        s0 = ffma2(q0p[4], kC.x, s0); s0 = ffma2(q0p[5], kC.y, s0);
        s0 = ffma2(q0p[6], kD.x, s0); s0 = ffma2(q0p[7], kD.y, s0);
        s1 = ffma2(q1p[0], kA.x, s1); s1 = ffma2(q1p[1], kA.y, s1);
        s1 = ffma2(q1p[2], kB.x, s1); s1 = ffma2(q1p[3], kB.y, s1);
        s1 = ffma2(q1p[4], kC.x, s1); s1 = ffma2(q1p[5], kC.y, s1);
        s1 = ffma2(q1p[6], kD.x, s1); s1 = ffma2(q1p[7], kD.y, s1);
        float2 s0f = u2f(s0);
        float2 s1f = u2f(s1);
        float e0 = __expf(s0f.x + s0f.y);
        float e1 = __expf(s1f.x + s1f.y);
        sum0 += e0; sum1 += e1;
        u64 e0p = f2u(e0, e0);
        u64 e1p = f2u(e1, e1);
        const ulonglong2* vr = (const ulonglong2*)(sV + (j << 4));
        ulonglong2 vA = vr[0], vB = vr[1], vC = vr[2], vD = vr[3];
        acc0[0] = ffma2(e0p, vA.x, acc0[0]); acc0[1] = ffma2(e0p, vA.y, acc0[1]);
        acc0[2] = ffma2(e0p, vB.x, acc0[2]); acc0[3] = ffma2(e0p, vB.y, acc0[3]);
        acc0[4] = ffma2(e0p, vC.x, acc0[4]); acc0[5] = ffma2(e0p, vC.y, acc0[5]);
        acc0[6] = ffma2(e0p, vD.x, acc0[6]); acc0[7] = ffma2(e0p, vD.y, acc0[7]);
        acc1[0] = ffma2(e1p, vA.x, acc1[0]); acc1[1] = ffma2(e1p, vA.y, acc1[1]);
        acc1[2] = ffma2(e1p, vB.x, acc1[2]); acc1[3] = ffma2(e1p, vB.y, acc1[3]);
        acc1[4] = ffma2(e1p, vC.x, acc1[4]); acc1[5] = ffma2(e1p, vC.y, acc1[5]);
        acc1[6] = ffma2(e1p, vD.x, acc1[6]); acc1[7] = ffma2(e1p, vD.y, acc1[7]);
    }
    float inv0 = 1.0f / sum0, inv1 = 1.0f / sum1;

    float a0f[16], a1f[16];
    #pragma unroll
    for (int i = 0; i < 8; i++) {
        float2 t0 = u2f(acc0[i]);
        a0f[2 * i] = t0.x; a0f[2 * i + 1] = t0.y;
        float2 t1 = u2f(acc1[i]);
        a1f[2 * i] = t1.x; a1f[2 * i + 1] = t1.y;
    }

    int Hsp = br ? 4 : 32;
    int Wsp = br ? 32 : 4;

    auto write_row = [&](int p, int ltok, const float* acc, float inv) {
        int ts = p >> 7, r2 = p & 127;
        int hs = br ? (r2 >> 5) : (r2 >> 2);
        int ws = r2 & (Wsp - 1);
        float lep[16];
        #pragma unroll
        for (int d = 0; d < 16; d++) lep[d] = sCB[d];
        #pragma unroll
        for (int kt = 0; kt < 3; kt++) {
            int t2 = ts + kt - 1;
            if ((unsigned)t2 >= 4u) continue;
            #pragma unroll
            for (int kh = 0; kh < 3; kh++) {
                int h2 = hs + kh - 1;
                if ((unsigned)h2 >= (unsigned)Hsp) continue;
                #pragma unroll
                for (int kw = 0; kw < 3; kw++) {
                    int w2 = ws + kw - 1;
                    if ((unsigned)w2 >= (unsigned)Wsp) continue;
                    int pp = (t2 * Hsp + h2) * Wsp + w2;
                    int kidx = kt * 9 + kh * 3 + kw;
                    const float4* wr4 = (const float4*)&sCW[kidx * 16];
                    const float4* vr4 = (const float4*)&sV[pp * 16];
                    #pragma unroll
                    for (int d4 = 0; d4 < 4; d4++) {
                        float4 wv = wr4[d4];
                        float4 vv = vr4[d4];
                        lep[d4*4+0] = fmaf(wv.x, vv.x, lep[d4*4+0]);
                        lep[d4*4+1] = fmaf(wv.y, vv.y, lep[d4*4+1]);
                        lep[d4*4+2] = fmaf(wv.z, vv.z, lep[d4*4+2]);
                        lep[d4*4+3] = fmaf(wv.w, vv.w, lep[d4*4+3]);
                    }
                }
            }
        }
        float* op = att + (size_t)(rowbase + ltok) * 128 + cq;
        #pragma unroll
        for (int d4 = 0; d4 < 4; d4++) {
            float4 o;
            o.x = acc[d4*4+0] * inv + lep[d4*4+0];
            o.y = acc[d4*4+1] * inv + lep[d4*4+1];
            o.z = acc[d4*4+2] * inv + lep[d4*4+2];
            o.w = acc[d4*4+3] * inv + lep[d4*4+3];
            *(float4*)(op + d4 * 4) = o;
        }
    };
    write_row(p0, l0t, a0f, inv0);
    write_row(p1, l1t, a1f, inv1);
}

// ---------------------------------------------------------------------------
// Launch sequence
// ---------------------------------------------------------------------------
extern "C" void kernel_launch(void* const* d_in, const int* in_sizes, int n_in,
                              void* d_out, int out_size)
{
    const float* x    = (const float*)d_in[0];
    const float* n1w  = (const float*)d_in[1];
    const float* n1b  = (const float*)d_in[2];
    const float* qkvw = (const float*)d_in[3];
    const float* cw0  = (const float*)d_in[4];
    const float* cb0  = (const float*)d_in[5];
    const float* cw1  = (const float*)d_in[6];
    const float* cb1  = (const float*)d_in[7];
    const float* pw   = (const float*)d_in[8];
    const float* pb   = (const float*)d_in[9];
    const float* n2w  = (const float*)d_in[10];
    const float* n2b  = (const float*)d_in[11];
    const float* f1w  = (const float*)d_in[12];
    const float* f1b  = (const float*)d_in[13];
    const float* f2w  = (const float*)d_in[14];
    const float* f2b  = (const float*)d_in[15];
    float* out = (float*)d_out;

    float *pnorm, *pqkv, *patt, *phid;
    cudaGetSymbolAddress((void**)&pnorm, g_norm);
    cudaGetSymbolAddress((void**)&pqkv,  g_qkv);
    cudaGetSymbolAddress((void**)&patt,  g_att);
    cudaGetSymbolAddress((void**)&phid,  g_hid);

    cudaFuncSetAttribute(attn_kernel,
                         cudaFuncAttributeMaxDynamicSharedMemorySize, 65536);

    // 1) LN1
    ln_kernel<<<4096, 256>>>(x, n1w, n1b, pnorm);
    // 2) qkv = LN1(x) @ qkv_w^T   (M x 384)
    gemm_kernel<false><<<dim3(6, 256), 256>>>(pnorm, qkvw, nullptr, nullptr,
                                              pqkv, 384, 128);
    // 3) windowed attention + LePE, both branches
    attn_kernel<<<512, 256, 65536>>>(pqkv, cw0, cb0, cw1, cb1, patt);
    // 4) x2 = x + att @ proj_w^T + proj_b  -> d_out
    gemm_kernel<false><<<dim3(2, 256), 256>>>(patt, pw, pb, x, out, 128, 128);
    // 5) LN2
    ln_kernel<<<4096, 256>>>(out, n2w, n2b, pnorm);
    // 6) hid = gelu(LN2 @ fc1_w^T + fc1_b)  (M x 512)
    gemm_kernel<true><<<dim3(8, 256), 256>>>(pnorm, f1w, f1b, nullptr,
                                             phid, 512, 128);
    // 7) out = x2 + hid @ fc2_w^T + fc2_b
    gemm_kernel<false><<<dim3(2, 256), 256>>>(phid, f2w, f2b, out, out, 128, 512);
}

// round 6
// speedup vs baseline: 1.8644x; 1.8644x over previous
#include <cuda_runtime.h>
#include <math.h>
#include <stdint.h>

// Shapes: B=4, T=8, RES=32, C=128 -> L=8192, M=32768 rows
// branch0: Hsp=32, Wsp=4 ; branch1: Hsp=4, Wsp=32 ; win=512, nh=4, hd=16

#define M_TOK 32768

typedef unsigned long long u64;

__device__ __forceinline__ u64 ffma2(u64 a, u64 b, u64 c) {
    u64 d;
    asm("fma.rn.f32x2 %0, %1, %2, %3;" : "=l"(d) : "l"(a), "l"(b), "l"(c));
    return d;
}
__device__ __forceinline__ u64 mul2(u64 a, u64 b) {
    u64 d;
    asm("mul.rn.f32x2 %0, %1, %2;" : "=l"(d) : "l"(a), "l"(b));
    return d;
}
__device__ __forceinline__ float2 u2f(u64 a) {
    float2 f;
    asm("mov.b64 {%0, %1}, %2;" : "=f"(f.x), "=f"(f.y) : "l"(a));
    return f;
}
__device__ __forceinline__ u64 f2u(float x, float y) {
    u64 d;
    asm("mov.b64 %0, {%1, %2};" : "=l"(d) : "f"(x), "f"(y));
    return d;
}
// round fp32 -> tf32 (round-to-nearest-even on 10-bit mantissa), keep fp32 bits
__device__ __forceinline__ float tf32r(float x) {
    uint32_t u;
    asm("cvt.rna.tf32.f32 %0, %1;" : "=r"(u) : "f"(x));
    return __uint_as_float(u);
}
// D(16x8,f32) += A(16x8,tf32 row) * B(8x8,tf32 col)
__device__ __forceinline__ void mma8(float c[4],
                                     uint32_t a0, uint32_t a1, uint32_t a2,
                                     uint32_t a3, uint32_t b0, uint32_t b1) {
    asm("mma.sync.aligned.m16n8k8.row.col.f32.tf32.tf32.f32 "
        "{%0,%1,%2,%3}, {%4,%5,%6,%7}, {%8,%9}, {%0,%1,%2,%3};"
        : "+f"(c[0]), "+f"(c[1]), "+f"(c[2]), "+f"(c[3])
        : "r"(a0), "r"(a1), "r"(a2), "r"(a3), "r"(b0), "r"(b1));
}

// Scratch (static device arrays; no runtime allocation)
__device__ float g_norm[M_TOK * 128];
__device__ float g_qkv [M_TOK * 384];
__device__ float g_att [M_TOK * 128];
__device__ float g_hid [M_TOK * 512];

// ---------------------------------------------------------------------------
// LayerNorm: one warp per 128-channel row
// ---------------------------------------------------------------------------
__global__ void __launch_bounds__(256) ln_kernel(
    const float* __restrict__ x, const float* __restrict__ w,
    const float* __restrict__ b, float* __restrict__ out)
{
    int lane = threadIdx.x & 31;
    int row  = blockIdx.x * 8 + (threadIdx.x >> 5);
    const float4 v = *(const float4*)(x + (size_t)row * 128 + lane * 4);
    float s = v.x + v.y + v.z + v.w;
    #pragma unroll
    for (int o = 16; o; o >>= 1) s += __shfl_xor_sync(0xffffffffu, s, o);
    float mu = s * (1.0f / 128.0f);
    float dx = v.x - mu, dy = v.y - mu, dz = v.z - mu, dw = v.w - mu;
    float sq = dx * dx + dy * dy + dz * dz + dw * dw;
    #pragma unroll
    for (int o = 16; o; o >>= 1) sq += __shfl_xor_sync(0xffffffffu, sq, o);
    float r = rsqrtf(sq * (1.0f / 128.0f) + 1e-5f);
    float4 wv = *(const float4*)(w + lane * 4);
    float4 bv = *(const float4*)(b + lane * 4);
    float4 o4;
    o4.x = dx * r * wv.x + bv.x;
    o4.y = dy * r * wv.y + bv.y;
    o4.z = dz * r * wv.z + bv.z;
    o4.w = dw * r * wv.w + bv.w;
    *(float4*)(out + (size_t)row * 128 + lane * 4) = o4;
}

// ---------------------------------------------------------------------------
// tf32 tensor-core GEMM: out[M,N] = A[M,K] @ W[N,K]^T (+bias)(+gelu)(+res)
// CTA tile 128x64, 8 warps (4x2), warp tile 32x32 = 2x4 m16n8k8 frags.
// BK=32 staged in SMEM (pad 36 -> conflict-free fragment loads).
// Inputs rounded to tf32 (rna) at staging; fp32 accumulate.
// ---------------------------------------------------------------------------
template <bool GELU>
__global__ void __launch_bounds__(256) mma_gemm(
    const float* __restrict__ A, const float* __restrict__ W,
    const float* __restrict__ bias, const float* __restrict__ res,
    float* __restrict__ out, int N, int K)
{
    __shared__ float sA[128][36];
    __shared__ float sW[64][36];

    const int tid  = threadIdx.x;
    const int m0   = blockIdx.y << 7, n0 = blockIdx.x << 6;
    const int warp = tid >> 5, lane = tid & 31;
    const int g    = lane >> 2, tig = lane & 3;
    const int wm   = warp >> 1, wn = warp & 1;

    float acc[2][4][4];
    #pragma unroll
    for (int mi = 0; mi < 2; mi++)
        #pragma unroll
        for (int ni = 0; ni < 4; ni++)
            #pragma unroll
            for (int q = 0; q < 4; q++) acc[mi][ni][q] = 0.f;

    const int srow = tid >> 3;        // 0..31
    const int skq  = (tid & 7) << 2;  // 0,4,...,28

    for (int k0 = 0; k0 < K; k0 += 32) {
        __syncthreads();
        // stage A: 128x32, tf32-rounded
        #pragma unroll
        for (int p = 0; p < 4; p++) {
            int r = srow + (p << 5);
            float4 v = *(const float4*)(A + (size_t)(m0 + r) * K + k0 + skq);
            sA[r][skq + 0] = tf32r(v.x);
            sA[r][skq + 1] = tf32r(v.y);
            sA[r][skq + 2] = tf32r(v.z);
            sA[r][skq + 3] = tf32r(v.w);
        }
        // stage W: 64x32
        #pragma unroll
        for (int p = 0; p < 2; p++) {
            int r = srow + (p << 5);
            float4 v = *(const float4*)(W + (size_t)(n0 + r) * K + k0 + skq);
            sW[r][skq + 0] = tf32r(v.x);
            sW[r][skq + 1] = tf32r(v.y);
            sW[r][skq + 2] = tf32r(v.z);
            sW[r][skq + 3] = tf32r(v.w);
        }
        __syncthreads();

        #pragma unroll
        for (int k8 = 0; k8 < 32; k8 += 8) {
            uint32_t bf[4][2];
            #pragma unroll
            for (int ni = 0; ni < 4; ni++) {
                int n = (wn << 5) + (ni << 3) + g;
                bf[ni][0] = __float_as_uint(sW[n][k8 + tig]);
                bf[ni][1] = __float_as_uint(sW[n][k8 + tig + 4]);
            }
            #pragma unroll
            for (int mi = 0; mi < 2; mi++) {
                int m = (wm << 5) + (mi << 4);
                uint32_t a0 = __float_as_uint(sA[m + g][k8 + tig]);
                uint32_t a1 = __float_as_uint(sA[m + g + 8][k8 + tig]);
                uint32_t a2 = __float_as_uint(sA[m + g][k8 + tig + 4]);
                uint32_t a3 = __float_as_uint(sA[m + g + 8][k8 + tig + 4]);
                #pragma unroll
                for (int ni = 0; ni < 4; ni++)
                    mma8(acc[mi][ni], a0, a1, a2, a3, bf[ni][0], bf[ni][1]);
            }
        }
    }

    // epilogue: c0=(g,2t) c1=(g,2t+1) c2=(g+8,2t) c3=(g+8,2t+1)
    #pragma unroll
    for (int mi = 0; mi < 2; mi++) {
        int r0 = m0 + (wm << 5) + (mi << 4) + g;
        int r1 = r0 + 8;
        #pragma unroll
        for (int ni = 0; ni < 4; ni++) {
            int col = n0 + (wn << 5) + (ni << 3) + (tig << 1);
            float b0 = 0.f, b1 = 0.f;
            if (bias) {
                float2 bb = *(const float2*)(bias + col);
                b0 = bb.x; b1 = bb.y;
            }
            float v00 = acc[mi][ni][0] + b0;
            float v01 = acc[mi][ni][1] + b1;
            float v10 = acc[mi][ni][2] + b0;
            float v11 = acc[mi][ni][3] + b1;
            if (GELU) {
                v00 = 0.5f * v00 * (1.0f + erff(v00 * 0.70710678118654752f));
                v01 = 0.5f * v01 * (1.0f + erff(v01 * 0.70710678118654752f));
                v10 = 0.5f * v10 * (1.0f + erff(v10 * 0.70710678118654752f));
                v11 = 0.5f * v11 * (1.0f + erff(v11 * 0.70710678118654752f));
            }
            size_t o0 = (size_t)r0 * N + col;
            size_t o1 = (size_t)r1 * N + col;
            if (res) {
                float2 q0 = *(const float2*)(res + o0);
                float2 q1 = *(const float2*)(res + o1);
                v00 += q0.x; v01 += q0.y;
                v10 += q1.x; v11 += q1.y;
            }
            float2 w0 = {v00, v01};
            float2 w1 = {v10, v11};
            *(float2*)(out + o0) = w0;
            *(float2*)(out + o1) = w1;
        }
    }
}

// ---------------------------------------------------------------------------
// Attention + fused LePE (proven in R4). One CTA per (branch, window, head).
// Single-pass softmax (|score| small, exp safe) with FFMA2 packed math.
// ---------------------------------------------------------------------------
__global__ void __launch_bounds__(256, 2) attn_kernel(
    const float* __restrict__ qkv,
    const float* __restrict__ cw0, const float* __restrict__ cb0,
    const float* __restrict__ cw1, const float* __restrict__ cb1,
    float* __restrict__ att)
{
    extern __shared__ float dsm[];
    float* sK = dsm;            // 512*16
    float* sV = dsm + 8192;     // 512*16
    __shared__ float sCW[27 * 16];
    __shared__ float sCB[16];

    int bid = blockIdx.x;
    int br  = bid >> 8;
    int rem = bid & 255;
    int w   = rem >> 2;
    int n   = rem & 3;
    int b   = w >> 4;
    int tb  = (w >> 3) & 1;
    int hw  = w & 7;
    int tid = threadIdx.x;

    auto tok = [&](int p) -> int {
        int ts = p >> 7, r2 = p & 127;
        if (br == 0) {
            int hs = r2 >> 2, ws = r2 & 3;
            return ((tb * 4 + ts) << 10) + (hs << 5) + (hw << 2) + ws;
        } else {
            int hs = r2 >> 5, ws = r2 & 31;
            return ((tb * 4 + ts) << 10) + (((hw << 2) + hs) << 5) + ws;
        }
    };

    int cq = br * 64 + n * 16;
    int rowbase = b * 8192;

    for (int idx = tid; idx < 2048; idx += 256) {
        int p = idx >> 2, c4 = (idx & 3) << 2;
        const float* base = qkv + (size_t)(rowbase + tok(p)) * 384;
        *(float4*)&sK[p * 16 + c4] = *(const float4*)(base + 128 + cq + c4);
        *(float4*)&sV[p * 16 + c4] = *(const float4*)(base + 256 + cq + c4);
    }
    {
        const float* cw = br ? cw1 : cw0;
        for (int idx = tid; idx < 432; idx += 256) {
            int d = idx / 27, k = idx - d * 27;
            sCW[k * 16 + d] = cw[(n * 16 + d) * 27 + k];
        }
        if (tid < 16) sCB[tid] = (br ? cb1 : cb0)[n * 16 + tid];
    }
    __syncthreads();

    int p0 = tid, p1 = tid + 256;
    int l0t = tok(p0), l1t = tok(p1);

    u64 q0p[8], q1p[8];
    {
        const u64 scale2 = f2u(0.25f, 0.25f);
        const ulonglong2* qv0 =
            (const ulonglong2*)(qkv + (size_t)(rowbase + l0t) * 384 + cq);
        const ulonglong2* qv1 =
            (const ulonglong2*)(qkv + (size_t)(rowbase + l1t) * 384 + cq);
        #pragma unroll
        for (int i = 0; i < 4; i++) {
            ulonglong2 t0 = qv0[i];
            q0p[2 * i]     = mul2(t0.x, scale2);
            q0p[2 * i + 1] = mul2(t0.y, scale2);
            ulonglong2 t1 = qv1[i];
            q1p[2 * i]     = mul2(t1.x, scale2);
            q1p[2 * i + 1] = mul2(t1.y, scale2);
        }
    }

    u64 acc0[8], acc1[8];
    #pragma unroll
    for (int i = 0; i < 8; i++) { acc0[i] = 0ull; acc1[i] = 0ull; }
    float sum0 = 0.f, sum1 = 0.f;

    #pragma unroll 2
    for (int j = 0; j < 512; j++) {
        const ulonglong2* kr = (const ulonglong2*)(sK + (j << 4));
        ulonglong2 kA = kr[0], kB = kr[1], kC = kr[2], kD = kr[3];
        u64 s0 = 0ull, s1 = 0ull;
        s0 = ffma2(q0p[0], kA.x, s0); s0 = ffma2(q0p[1], kA.y, s0);
        s0 = ffma2(q0p[2], kB.x, s0); s0 = ffma2(q0p[3], kB.y, s0);
        s0 = ffma2(q0p[4], kC.x, s0); s0 = ffma2(q0p[5], kC.y, s0);
        s0 = ffma2(q0p[6], kD.x, s0); s0 = ffma2(q0p[7], kD.y, s0);
        s1 = ffma2(q1p[0], kA.x, s1); s1 = ffma2(q1p[1], kA.y, s1);
        s1 = ffma2(q1p[2], kB.x, s1); s1 = ffma2(q1p[3], kB.y, s1);
        s1 = ffma2(q1p[4], kC.x, s1); s1 = ffma2(q1p[5], kC.y, s1);
        s1 = ffma2(q1p[6], kD.x, s1); s1 = ffma2(q1p[7], kD.y, s1);
        float2 s0f = u2f(s0);
        float2 s1f = u2f(s1);
        float e0 = __expf(s0f.x + s0f.y);
        float e1 = __expf(s1f.x + s1f.y);
        sum0 += e0; sum1 += e1;
        u64 e0p = f2u(e0, e0);
        u64 e1p = f2u(e1, e1);
        const ulonglong2* vr = (const ulonglong2*)(sV + (j << 4));
        ulonglong2 vA = vr[0], vB = vr[1], vC = vr[2], vD = vr[3];
        acc0[0] = ffma2(e0p, vA.x, acc0[0]); acc0[1] = ffma2(e0p, vA.y, acc0[1]);
        acc0[2] = ffma2(e0p, vB.x, acc0[2]); acc0[3] = ffma2(e0p, vB.y, acc0[3]);
        acc0[4] = ffma2(e0p, vC.x, acc0[4]); acc0[5] = ffma2(e0p, vC.y, acc0[5]);
        acc0[6] = ffma2(e0p, vD.x, acc0[6]); acc0[7] = ffma2(e0p, vD.y, acc0[7]);
        acc1[0] = ffma2(e1p, vA.x, acc1[0]); acc1[1] = ffma2(e1p, vA.y, acc1[1]);
        acc1[2] = ffma2(e1p, vB.x, acc1[2]); acc1[3] = ffma2(e1p, vB.y, acc1[3]);
        acc1[4] = ffma2(e1p, vC.x, acc1[4]); acc1[5] = ffma2(e1p, vC.y, acc1[5]);
        acc1[6] = ffma2(e1p, vD.x, acc1[6]); acc1[7] = ffma2(e1p, vD.y, acc1[7]);
    }
    float inv0 = 1.0f / sum0, inv1 = 1.0f / sum1;

    float a0f[16], a1f[16];
    #pragma unroll
    for (int i = 0; i < 8; i++) {
        float2 t0 = u2f(acc0[i]);
        a0f[2 * i] = t0.x; a0f[2 * i + 1] = t0.y;
        float2 t1 = u2f(acc1[i]);
        a1f[2 * i] = t1.x; a1f[2 * i + 1] = t1.y;
    }

    int Hsp = br ? 4 : 32;
    int Wsp = br ? 32 : 4;

    auto write_row = [&](int p, int ltok, const float* acc, float inv) {
        int ts = p >> 7, r2 = p & 127;
        int hs = br ? (r2 >> 5) : (r2 >> 2);
        int ws = r2 & (Wsp - 1);
        float lep[16];
        #pragma unroll
        for (int d = 0; d < 16; d++) lep[d] = sCB[d];
        #pragma unroll
        for (int kt = 0; kt < 3; kt++) {
            int t2 = ts + kt - 1;
            if ((unsigned)t2 >= 4u) continue;
            #pragma unroll
            for (int kh = 0; kh < 3; kh++) {
                int h2 = hs + kh - 1;
                if ((unsigned)h2 >= (unsigned)Hsp) continue;
                #pragma unroll
                for (int kw = 0; kw < 3; kw++) {
                    int w2 = ws + kw - 1;
                    if ((unsigned)w2 >= (unsigned)Wsp) continue;
                    int pp = (t2 * Hsp + h2) * Wsp + w2;
                    int kidx = kt * 9 + kh * 3 + kw;
                    const float4* wr4 = (const float4*)&sCW[kidx * 16];
                    const float4* vr4 = (const float4*)&sV[pp * 16];
                    #pragma unroll
                    for (int d4 = 0; d4 < 4; d4++) {
                        float4 wv = wr4[d4];
                        float4 vv = vr4[d4];
                        lep[d4*4+0] = fmaf(wv.x, vv.x, lep[d4*4+0]);
                        lep[d4*4+1] = fmaf(wv.y, vv.y, lep[d4*4+1]);
                        lep[d4*4+2] = fmaf(wv.z, vv.z, lep[d4*4+2]);
                        lep[d4*4+3] = fmaf(wv.w, vv.w, lep[d4*4+3]);
                    }
                }
            }
        }
        float* op = att + (size_t)(rowbase + ltok) * 128 + cq;
        #pragma unroll
        for (int d4 = 0; d4 < 4; d4++) {
            float4 o;
            o.x = acc[d4*4+0] * inv + lep[d4*4+0];
            o.y = acc[d4*4+1] * inv + lep[d4*4+1];
            o.z = acc[d4*4+2] * inv + lep[d4*4+2];
            o.w = acc[d4*4+3] * inv + lep[d4*4+3];
            *(float4*)(op + d4 * 4) = o;
        }
    };
    write_row(p0, l0t, a0f, inv0);
    write_row(p1, l1t, a1f, inv1);
}

// ---------------------------------------------------------------------------
// Launch sequence
// ---------------------------------------------------------------------------
extern "C" void kernel_launch(void* const* d_in, const int* in_sizes, int n_in,
                              void* d_out, int out_size)
{
    const float* x    = (const float*)d_in[0];
    const float* n1w  = (const float*)d_in[1];
    const float* n1b  = (const float*)d_in[2];
    const float* qkvw = (const float*)d_in[3];
    const float* cw0  = (const float*)d_in[4];
    const float* cb0  = (const float*)d_in[5];
    const float* cw1  = (const float*)d_in[6];
    const float* cb1  = (const float*)d_in[7];
    const float* pw   = (const float*)d_in[8];
    const float* pb   = (const float*)d_in[9];
    const float* n2w  = (const float*)d_in[10];
    const float* n2b  = (const float*)d_in[11];
    const float* f1w  = (const float*)d_in[12];
    const float* f1b  = (const float*)d_in[13];
    const float* f2w  = (const float*)d_in[14];
    const float* f2b  = (const float*)d_in[15];
    float* out = (float*)d_out;

    float *pnorm, *pqkv, *patt, *phid;
    cudaGetSymbolAddress((void**)&pnorm, g_norm);
    cudaGetSymbolAddress((void**)&pqkv,  g_qkv);
    cudaGetSymbolAddress((void**)&patt,  g_att);
    cudaGetSymbolAddress((void**)&phid,  g_hid);

    cudaFuncSetAttribute(attn_kernel,
                         cudaFuncAttributeMaxDynamicSharedMemorySize, 65536);

    // 1) LN1
    ln_kernel<<<4096, 256>>>(x, n1w, n1b, pnorm);
    // 2) qkv = LN1(x) @ qkv_w^T   (M x 384)
    mma_gemm<false><<<dim3(6, 256), 256>>>(pnorm, qkvw, nullptr, nullptr,
                                           pqkv, 384, 128);
    // 3) windowed attention + LePE, both branches
    attn_kernel<<<512, 256, 65536>>>(pqkv, cw0, cb0, cw1, cb1, patt);
    // 4) x2 = x + att @ proj_w^T + proj_b  -> d_out
    mma_gemm<false><<<dim3(2, 256), 256>>>(patt, pw, pb, x, out, 128, 128);
    // 5) LN2
    ln_kernel<<<4096, 256>>>(out, n2w, n2b, pnorm);
    // 6) hid = gelu(LN2 @ fc1_w^T + fc1_b)  (M x 512)
    mma_gemm<true><<<dim3(8, 256), 256>>>(pnorm, f1w, f1b, nullptr,
                                          phid, 512, 128);
    // 7) out = x2 + hid @ fc2_w^T + fc2_b
    mma_gemm<false><<<dim3(2, 256), 256>>>(phid, f2w, f2b, out, out, 128, 512);
}